// round 6
// baseline (speedup 1.0000x reference)
#include <cuda_runtime.h>

#define Nn 8192
#define Dd 1024
#define BATCH 32

typedef unsigned long long ull;

// Persistent scratch. g_pre[j] = PRE-activation of skips[j], j=0..7.
__device__ float g_pre[8][BATCH][Dd];

__device__ __forceinline__ void fma2(ull& d, ull a, ull b) {
    asm("fma.rn.f32x2 %0, %1, %2, %0;" : "+l"(d) : "l"(a), "l"(b));
}
__device__ __forceinline__ void red4(float* p, float a, float b, float c, float d) {
    asm volatile("red.global.add.v4.f32 [%0], {%1,%2,%3,%4};"
                 :: "l"(p), "f"(a), "f"(b), "f"(c), "f"(d) : "memory");
}
__device__ __forceinline__ unsigned s2u(const void* p) {
    return (unsigned)__cvta_generic_to_shared(p);
}
__device__ __forceinline__ void cpa16(unsigned dst, const void* src) {
    asm volatile("cp.async.cg.shared.global [%0], [%1], 16;" :: "r"(dst), "l"(src));
}
__device__ __forceinline__ float sig(float v) {
    return 1.f / (1.f + __expf(-v));
}

// ---------------------------------------------------------------------------
// Masked matvec block (simple, occupancy-oriented):
//   out[b, d0+d] += sum_n act(X[b,n]) * W[d0+d,n] * (adjA[n*Nn + d0+d] != 0)
// 256 threads, tile 64d x 64n, ntiles iterations.
// Per tile: cp.async W[d][n] + adj[n][d] into single smem buffers (no
// register prefetch, no double buffer), small X LDG, mask W in place, FFMA2.
// Latency hiding comes from 4 co-resident blocks per SM, not in-block
// pipelining.
// ---------------------------------------------------------------------------
template <bool SIG>
__device__ __forceinline__ void mv_block(
    const float* __restrict__ W, int wstride,
    const int* __restrict__ adjA,          // adj + rowoff*Nn + colbase
    const float* __restrict__ X, int xstride,
    float* __restrict__ out,               // [32][1024]
    int d0, int n0, int ntiles)
{
    __shared__ float ws[64 * 68];          // [d][n] pitch 68 floats (17.4KB)
    __shared__ int   adjI[64 * 68];        // [n][d] pitch 68 ints   (17.4KB)
    __shared__ float4 hs[16][33];          // [nq][b]                (2.1KB)

    const int t    = threadIdx.x;
    const int warp = t >> 5, lane = t & 31;
    const int nf   = t & 15;               // 4-wide column group
    const int dr   = t >> 4;               // 0..15

    ull acc2[8];
#pragma unroll
    for (int j = 0; j < 8; j++) acc2[j] = 0ull;

    for (int tt = 0; tt < ntiles; tt++) {
        const int nb = n0 + tt * 64;

        if (tt) __syncthreads();           // prev FFMA done before overwrite

        // async-copy W tile (coalesced over n) and adj tile (coalesced over d)
#pragma unroll
        for (int ii = 0; ii < 4; ii++) {
            int d = ii * 16 + dr;
            cpa16(s2u(&ws[d * 68 + nf * 4]),
                  &W[(size_t)(d0 + d) * wstride + nb + nf * 4]);
        }
#pragma unroll
        for (int ii = 0; ii < 4; ii++) {
            int n = ii * 16 + dr;
            cpa16(s2u(&adjI[n * 68 + nf * 4]),
                  &adjA[(size_t)(nb + n) * Nn + d0 + nf * 4]);
        }
        asm volatile("cp.async.commit_group;");

        // X slice via LDG (registers), activation applied on store
        float4 xv0 = *(const float4*)&X[(size_t)(dr)      * xstride + nb + nf * 4];
        float4 xv1 = *(const float4*)&X[(size_t)(dr + 16) * xstride + nb + nf * 4];

        asm volatile("cp.async.wait_group 0;");
        __syncthreads();

        if (SIG) {
            xv0.x = sig(xv0.x); xv0.y = sig(xv0.y); xv0.z = sig(xv0.z); xv0.w = sig(xv0.w);
            xv1.x = sig(xv1.x); xv1.y = sig(xv1.y); xv1.z = sig(xv1.z); xv1.w = sig(xv1.w);
        }
        hs[nf][dr]      = xv0;
        hs[nf][dr + 16] = xv1;

        // mask W in place: wm[d][n] = ws[d][n] * (adjI[n][d] != 0)
#pragma unroll
        for (int ii = 0; ii < 4; ii++) {
            int d = ii * 16 + dr;
            float4 wv = *(const float4*)&ws[d * 68 + nf * 4];
            float4 o;
            o.x = adjI[(nf * 4 + 0) * 68 + d] ? wv.x : 0.f;
            o.y = adjI[(nf * 4 + 1) * 68 + d] ? wv.y : 0.f;
            o.z = adjI[(nf * 4 + 2) * 68 + d] ? wv.z : 0.f;
            o.w = adjI[(nf * 4 + 3) * 68 + d] ? wv.w : 0.f;
            *(float4*)&ws[d * 68 + nf * 4] = o;
        }
        __syncthreads();

        // FFMA2 phase: lane = batch, warp owns 8 d's
        const int dbase = warp * 8;
#pragma unroll
        for (int nq = 0; nq < 16; nq++) {
            ulonglong2 hv = *(const ulonglong2*)&hs[nq][lane];
#pragma unroll
            for (int j = 0; j < 8; j++) {
                ulonglong2 w2 = *(const ulonglong2*)&ws[(dbase + j) * 68 + nq * 4];
                fma2(acc2[j], hv.x, w2.x);
                fma2(acc2[j], hv.y, w2.y);
            }
        }
    }

    float r[8];
#pragma unroll
    for (int j = 0; j < 8; j++) {
        float2 f = *(float2*)&acc2[j];
        r[j] = f.x + f.y;
    }
    float* op = &out[lane * Dd + d0 + warp * 8];
    red4(op,     r[0], r[1], r[2], r[3]);
    red4(op + 4, r[4], r[5], r[6], r[7]);
}

// ---------------------------------------------------------------------------

// g_pre[0][b][d] = b_in[d]; g_pre[i][b][d] = b_h[i-1][d] for i=1..7
__global__ void init_kernel(const float* __restrict__ b_in,
                            const float* __restrict__ b_h) {
    int idx = blockIdx.x * 256 + threadIdx.x;   // 1024 blocks
    int d = idx & 1023, i = idx >> 15;
    ((float*)g_pre)[idx] = (i == 0) ? b_in[d] : b_h[(i - 1) * Dd + d];
}

// g_pre[0] += h @ Wr_m(0).T  (n >= 1024). grid (16, 7, 8), ntiles=2.
__global__ void __launch_bounds__(256, 4) r0_kernel(
    const float* __restrict__ W_r, const int* __restrict__ adj,
    const float* __restrict__ h)
{
    mv_block<false>(W_r, Nn, adj, h, Nn, &g_pre[0][0][0],
                    blockIdx.x * 64, (1 + blockIdx.y) * 1024 + blockIdx.z * 128, 2);
}

// g_pre[0] += x @ W_in.T
__global__ void prelayer_kernel(
    const float* __restrict__ x, const float* __restrict__ W_in)
{
    int idx = blockIdx.x * 256 + threadIdx.x;  // 32768
    int d = idx & 1023, bt = idx >> 10;
    const float4* xr = (const float4*)(x + bt * 256);
    const float4* wr = (const float4*)(W_in + (size_t)d * 256);
    float s = 0.f;
#pragma unroll 8
    for (int c = 0; c < 64; c++) {
        float4 aa = xr[c], bb = wr[c];
        s += aa.x * bb.x + aa.y * bb.y + aa.z * bb.z + aa.w * bb.w;
    }
    g_pre[0][bt][d] += s;
}

// Fused launch after g_pre[j] is complete. grid (16, 13-2j, zc):
//   y == 0          : pre[j+1] += sig(pre[j]) @ Wh_m(j).T
//   y in [1, 7-j)   : pre[i+1] += sig(pre[j]) @ Ws-block(i, j).T   (i = j+y)
//   y in [7-j,13-2j): pre[j+1] += h @ Wr_m(j+1).T slice
__global__ void __launch_bounds__(256, 4) L_kernel(
    const float* __restrict__ W_h, const float* __restrict__ W_s,
    const float* __restrict__ W_r, const int* __restrict__ adj,
    const float* __restrict__ h, int j, int ntiles)
{
    int d0 = blockIdx.x * 64;
    int y = blockIdx.y, z = blockIdx.z;
    int nloc = z * 64 * ntiles;
    if (y == 0) {
        mv_block<true>(W_h + (size_t)j * Dd * Dd, Dd,
                       adj + (size_t)j * Dd * Nn + (j + 1) * Dd,
                       &g_pre[j][0][0], Dd,
                       &g_pre[j + 1][0][0], d0, nloc, ntiles);
    } else if (y <= 6 - j) {
        int i = j + y;   // target layer j+1..6
        // X rebased so X[b*Dd + n] == g_pre[j][b][n - j*1024]
        mv_block<true>(W_s + (size_t)(i - 1) * Dd * 6144, 6144,
                       adj + (i + 1) * Dd,
                       &g_pre[j][0][0] - j * 1024, Dd,
                       &g_pre[i + 1][0][0], d0, j * 1024 + nloc, ntiles);
    } else {
        int u = y - (7 - j);           // 0..5-j
        int k = j + 1;
        mv_block<false>(W_r + (size_t)k * Dd * Nn, Nn,
                        adj + k * Dd,
                        h, Nn,
                        &g_pre[j + 1][0][0], d0, (k + 1 + u) * 1024 + nloc, ntiles);
    }
}

// out = sig(g_pre[7]) @ W_o.T + b_o
__global__ void final_kernel(const float* __restrict__ W_o,
                             const float* __restrict__ b_o,
                             float* __restrict__ out)
{
    int idx = blockIdx.x * 256 + threadIdx.x;  // 2048
    int o = idx & 63, bt = idx >> 6;
    const float4* sr = (const float4*)&g_pre[7][bt][0];
    const float4* wr = (const float4*)(W_o + (size_t)o * Dd);
    float s = 0.f;
#pragma unroll 8
    for (int c = 0; c < 256; c++) {
        float4 aa = sr[c], bb = wr[c];
        s += sig(aa.x) * bb.x + sig(aa.y) * bb.y + sig(aa.z) * bb.z + sig(aa.w) * bb.w;
    }
    out[bt * 64 + o] = s + b_o[o];
}

// ---------------------------------------------------------------------------

extern "C" void kernel_launch(void* const* d_in, const int* in_sizes, int n_in,
                              void* d_out, int out_size)
{
    const float* x    = (const float*)d_in[0];
    const float* h    = (const float*)d_in[1];
    const int*   adj  = (const int*)d_in[2];
    const float* W_in = (const float*)d_in[3];
    const float* b_in = (const float*)d_in[4];
    const float* W_h  = (const float*)d_in[5];
    const float* b_h  = (const float*)d_in[6];
    const float* W_r  = (const float*)d_in[7];
    const float* W_s  = (const float*)d_in[8];
    const float* W_o  = (const float*)d_in[9];
    const float* b_o  = (const float*)d_in[10];
    float* out = (float*)d_out;

    init_kernel<<<1024, 256>>>(b_in, b_h);
    r0_kernel<<<dim3(16, 7, 8), 256>>>(W_r, adj, h);
    prelayer_kernel<<<128, 256>>>(x, W_in);

    for (int j = 0; j < 7; j++) {
        int zc = (j <= 3) ? 8 : 16;         // tail layers: more, smaller chunks
        int nt = (j <= 3) ? 2 : 1;
        L_kernel<<<dim3(16, 13 - 2 * j, zc), 256>>>(W_h, W_s, W_r, adj, h, j, nt);
    }

    final_kernel<<<8, 256>>>(W_o, b_o, out);
}

// round 7
// speedup vs baseline: 1.2180x; 1.2180x over previous
#include <cuda_runtime.h>

#define Nn 8192
#define Dd 1024
#define BATCH 32

typedef unsigned long long ull;

// Persistent scratch. g_pre[j] = PRE-activation of skips[j], j=0..7.
__device__ float g_pre[8][BATCH][Dd];

__device__ __forceinline__ void fma2(ull& d, ull a, ull b) {
    asm("fma.rn.f32x2 %0, %1, %2, %0;" : "+l"(d) : "l"(a), "l"(b));
}
__device__ __forceinline__ void red4(float* p, float a, float b, float c, float d) {
    asm volatile("red.global.add.v4.f32 [%0], {%1,%2,%3,%4};"
                 :: "l"(p), "f"(a), "f"(b), "f"(c), "f"(d) : "memory");
}
__device__ __forceinline__ unsigned s2u(const void* p) {
    return (unsigned)__cvta_generic_to_shared(p);
}
__device__ __forceinline__ void cpa16(unsigned dst, const void* src) {
    asm volatile("cp.async.cg.shared.global [%0], [%1], 16;" :: "r"(dst), "l"(src));
}
__device__ __forceinline__ float sig(float v) {
    return 1.f / (1.f + __expf(-v));
}

// Single shared workspace per block (declared ONCE in each kernel and passed
// by pointer so inlining mv_block at several call sites cannot duplicate it).
struct Smem {
    float         ws[64 * 68];        // [d][n] pitch 68 floats  (17.4 KB)
    unsigned char adjs[64 * 68];      // [n][d] bytes, pitch 68  ( 4.3 KB)
    float4        hs[16][33];         // [nq][b]                 ( 2.1 KB)
};                                    // total ~23.9 KB -> 4 blocks/SM

// ---------------------------------------------------------------------------
// Masked matvec block:
//   out[b, d0+d] += sum_n act(X[b,n]) * W[d0+d,n] * (adjA[n*Nn + d0+d] != 0)
// 256 threads, tile 64d x 64n, ntiles iterations.
// W via cp.async into smem; adj via int4 LDG -> byte STS (transpose);
// mask W in place; FFMA2 inner loop. Latency hidden by 4 blocks/SM.
// ---------------------------------------------------------------------------
template <bool SIG>
__device__ __forceinline__ void mv_block(
    Smem* sm,
    const float* __restrict__ W, int wstride,
    const int* __restrict__ adjA,          // adj + rowoff*Nn + colbase
    const float* __restrict__ X, int xstride,
    float* __restrict__ out,               // [32][1024]
    int d0, int n0, int ntiles)
{
    const int t    = threadIdx.x;
    const int warp = t >> 5, lane = t & 31;
    const int nf   = t & 15;               // 4-wide column group
    const int dr   = t >> 4;               // 0..15

    ull acc2[8];
#pragma unroll
    for (int j = 0; j < 8; j++) acc2[j] = 0ull;

    for (int tt = 0; tt < ntiles; tt++) {
        const int nb = n0 + tt * 64;

        if (tt) __syncthreads();           // prev FFMA done before overwrite

        // W tile via cp.async (coalesced over n)
#pragma unroll
        for (int ii = 0; ii < 4; ii++) {
            int d = ii * 16 + dr;
            cpa16(s2u(&sm->ws[d * 68 + nf * 4]),
                  &W[(size_t)(d0 + d) * wstride + nb + nf * 4]);
        }
        asm volatile("cp.async.commit_group;");

        // adj tile via LDG int4 (coalesced over d), X slice via LDG
        int4 a[4];
#pragma unroll
        for (int ii = 0; ii < 4; ii++) {
            int n = ii * 16 + dr;
            a[ii] = *(const int4*)&adjA[(size_t)(nb + n) * Nn + d0 + nf * 4];
        }
        float4 xv0 = *(const float4*)&X[(size_t)(dr)      * xstride + nb + nf * 4];
        float4 xv1 = *(const float4*)&X[(size_t)(dr + 16) * xstride + nb + nf * 4];

        // stage adj as bytes + activations
#pragma unroll
        for (int ii = 0; ii < 4; ii++) {
            int n = ii * 16 + dr;
            uchar4 u = make_uchar4((unsigned char)a[ii].x, (unsigned char)a[ii].y,
                                   (unsigned char)a[ii].z, (unsigned char)a[ii].w);
            *(uchar4*)&sm->adjs[n * 68 + nf * 4] = u;
        }
        if (SIG) {
            xv0.x = sig(xv0.x); xv0.y = sig(xv0.y); xv0.z = sig(xv0.z); xv0.w = sig(xv0.w);
            xv1.x = sig(xv1.x); xv1.y = sig(xv1.y); xv1.z = sig(xv1.z); xv1.w = sig(xv1.w);
        }
        sm->hs[nf][dr]      = xv0;
        sm->hs[nf][dr + 16] = xv1;

        asm volatile("cp.async.wait_group 0;");
        __syncthreads();

        // mask W in place: ws[d][n] *= (adjs[n][d] != 0)
#pragma unroll
        for (int ii = 0; ii < 4; ii++) {
            int d = ii * 16 + dr;
            float4 wv = *(const float4*)&sm->ws[d * 68 + nf * 4];
            float4 o;
            o.x = sm->adjs[(nf * 4 + 0) * 68 + d] ? wv.x : 0.f;
            o.y = sm->adjs[(nf * 4 + 1) * 68 + d] ? wv.y : 0.f;
            o.z = sm->adjs[(nf * 4 + 2) * 68 + d] ? wv.z : 0.f;
            o.w = sm->adjs[(nf * 4 + 3) * 68 + d] ? wv.w : 0.f;
            *(float4*)&sm->ws[d * 68 + nf * 4] = o;
        }
        __syncthreads();

        // FFMA2 phase: lane = batch, warp owns 8 d's
        const int dbase = warp * 8;
#pragma unroll
        for (int nq = 0; nq < 16; nq++) {
            ulonglong2 hv = *(const ulonglong2*)&sm->hs[nq][lane];
#pragma unroll
            for (int j = 0; j < 8; j++) {
                ulonglong2 w2 = *(const ulonglong2*)&sm->ws[(dbase + j) * 68 + nq * 4];
                fma2(acc2[j], hv.x, w2.x);
                fma2(acc2[j], hv.y, w2.y);
            }
        }
    }

    float r[8];
#pragma unroll
    for (int j = 0; j < 8; j++) {
        float2 f = *(float2*)&acc2[j];
        r[j] = f.x + f.y;
    }
    float* op = &out[lane * Dd + d0 + warp * 8];
    red4(op,     r[0], r[1], r[2], r[3]);
    red4(op + 4, r[4], r[5], r[6], r[7]);
}

// ---------------------------------------------------------------------------

// g_pre[0][b][d] = b_in[d]; g_pre[i][b][d] = b_h[i-1][d] for i=1..7
__global__ void init_kernel(const float* __restrict__ b_in,
                            const float* __restrict__ b_h) {
    int idx = blockIdx.x * 256 + threadIdx.x;   // 1024 blocks
    int d = idx & 1023, i = idx >> 15;
    ((float*)g_pre)[idx] = (i == 0) ? b_in[d] : b_h[(i - 1) * Dd + d];
}

// g_pre[0] += h @ Wr_m(0).T  (n >= 1024). grid (16, 7, 8), ntiles=2.
__global__ void __launch_bounds__(256, 4) r0_kernel(
    const float* __restrict__ W_r, const int* __restrict__ adj,
    const float* __restrict__ h)
{
    __shared__ Smem sm;
    mv_block<false>(&sm, W_r, Nn, adj, h, Nn, &g_pre[0][0][0],
                    blockIdx.x * 64, (1 + blockIdx.y) * 1024 + blockIdx.z * 128, 2);
}

// g_pre[0] += x @ W_in.T
__global__ void prelayer_kernel(
    const float* __restrict__ x, const float* __restrict__ W_in)
{
    int idx = blockIdx.x * 256 + threadIdx.x;  // 32768
    int d = idx & 1023, bt = idx >> 10;
    const float4* xr = (const float4*)(x + bt * 256);
    const float4* wr = (const float4*)(W_in + (size_t)d * 256);
    float s = 0.f;
#pragma unroll 8
    for (int c = 0; c < 64; c++) {
        float4 aa = xr[c], bb = wr[c];
        s += aa.x * bb.x + aa.y * bb.y + aa.z * bb.z + aa.w * bb.w;
    }
    g_pre[0][bt][d] += s;
}

// Fused launch after g_pre[j] is complete. grid (16, 13-2j, zc):
//   y == 0          : pre[j+1] += sig(pre[j]) @ Wh_m(j).T
//   y in [1, 7-j)   : pre[i+1] += sig(pre[j]) @ Ws-block(i, j).T   (i = j+y)
//   y in [7-j,13-2j): pre[j+1] += h @ Wr_m(j+1).T slice
__global__ void __launch_bounds__(256, 4) L_kernel(
    const float* __restrict__ W_h, const float* __restrict__ W_s,
    const float* __restrict__ W_r, const int* __restrict__ adj,
    const float* __restrict__ h, int j, int ntiles)
{
    __shared__ Smem sm;
    int d0 = blockIdx.x * 64;
    int y = blockIdx.y, z = blockIdx.z;
    int nloc = z * 64 * ntiles;
    if (y == 0) {
        mv_block<true>(&sm, W_h + (size_t)j * Dd * Dd, Dd,
                       adj + (size_t)j * Dd * Nn + (j + 1) * Dd,
                       &g_pre[j][0][0], Dd,
                       &g_pre[j + 1][0][0], d0, nloc, ntiles);
    } else if (y <= 6 - j) {
        int i = j + y;   // target layer j+1..6
        // X rebased so X[b*Dd + n] == g_pre[j][b][n - j*1024]
        mv_block<true>(&sm, W_s + (size_t)(i - 1) * Dd * 6144, 6144,
                       adj + (i + 1) * Dd,
                       &g_pre[j][0][0] - j * 1024, Dd,
                       &g_pre[i + 1][0][0], d0, j * 1024 + nloc, ntiles);
    } else {
        int u = y - (7 - j);           // 0..5-j
        int k = j + 1;
        mv_block<false>(&sm, W_r + (size_t)k * Dd * Nn, Nn,
                        adj + k * Dd,
                        h, Nn,
                        &g_pre[j + 1][0][0], d0, (k + 1 + u) * 1024 + nloc, ntiles);
    }
}

// out = sig(g_pre[7]) @ W_o.T + b_o
__global__ void final_kernel(const float* __restrict__ W_o,
                             const float* __restrict__ b_o,
                             float* __restrict__ out)
{
    int idx = blockIdx.x * 256 + threadIdx.x;  // 2048
    int o = idx & 63, bt = idx >> 6;
    const float4* sr = (const float4*)&g_pre[7][bt][0];
    const float4* wr = (const float4*)(W_o + (size_t)o * Dd);
    float s = 0.f;
#pragma unroll 8
    for (int c = 0; c < 256; c++) {
        float4 aa = sr[c], bb = wr[c];
        s += sig(aa.x) * bb.x + sig(aa.y) * bb.y + sig(aa.z) * bb.z + sig(aa.w) * bb.w;
    }
    out[bt * 64 + o] = s + b_o[o];
}

// ---------------------------------------------------------------------------

extern "C" void kernel_launch(void* const* d_in, const int* in_sizes, int n_in,
                              void* d_out, int out_size)
{
    const float* x    = (const float*)d_in[0];
    const float* h    = (const float*)d_in[1];
    const int*   adj  = (const int*)d_in[2];
    const float* W_in = (const float*)d_in[3];
    const float* b_in = (const float*)d_in[4];
    const float* W_h  = (const float*)d_in[5];
    const float* b_h  = (const float*)d_in[6];
    const float* W_r  = (const float*)d_in[7];
    const float* W_s  = (const float*)d_in[8];
    const float* W_o  = (const float*)d_in[9];
    const float* b_o  = (const float*)d_in[10];
    float* out = (float*)d_out;

    init_kernel<<<1024, 256>>>(b_in, b_h);
    r0_kernel<<<dim3(16, 7, 8), 256>>>(W_r, adj, h);
    prelayer_kernel<<<128, 256>>>(x, W_in);

    for (int j = 0; j < 7; j++) {
        int zc = (j <= 3) ? 8 : 16;         // tail layers: more, smaller chunks
        int nt = (j <= 3) ? 2 : 1;
        L_kernel<<<dim3(16, 13 - 2 * j, zc), 256>>>(W_h, W_s, W_r, adj, h, j, nt);
    }

    final_kernel<<<8, 256>>>(W_o, b_o, out);
}